// round 11
// baseline (speedup 1.0000x reference)
#include <cuda_runtime.h>

#define IN_DIM 256
#define FEAT   33152      // 256 + (256 + 256*256)/2 = 259 * 128
#define NB     8          // batch
#define NROWS  8192       // NHEAD * S * D_MODEL
#define NCHUNK 259        // 128-float chunks
#define OUTF   64

typedef unsigned long long u64;

// scratch (allocation-free rule: __device__ globals)
__device__ __align__(16) float g_feats[NB * FEAT];
__device__ __align__(16) float g_part[2][NB * NROWS];

// packed dual-FMA: d.lo = a.lo*b.lo + c.lo ; d.hi = a.hi*b.hi + c.hi
__device__ __forceinline__ u64 ffma2(u64 a, u64 b, u64 c) {
    u64 d;
    asm("fma.rn.f32x2 %0, %1, %2, %3;" : "=l"(d) : "l"(a), "l"(b), "l"(c));
    return d;
}

__device__ __forceinline__ float sum2(u64 v) {
    union { u64 u; float f[2]; } cvt;
    cvt.u = v;
    return cvt.f[0] + cvt.f[1];
}

// streaming (evict-first) 16B load for the 1-GB W stream
__device__ __forceinline__ ulonglong2 ldcs128(const void* p) {
    ulonglong2 v;
    asm volatile("ld.global.cs.v2.u64 {%0, %1}, [%2];"
                 : "=l"(v.x), "=l"(v.y) : "l"(p));
    return v;
}

// default-cached (L1-resident) 16B load for feats
__device__ __forceinline__ ulonglong2 ldca128(const void* p) {
    ulonglong2 v;
    asm("ld.global.ca.v2.u64 {%0, %1}, [%2];"
        : "=l"(v.x), "=l"(v.y) : "l"(p));
    return v;
}

// ---------------------------------------------------------------------------
// Kernel A: build feats = [x_flat | triu(x x^T)] for all 8 batches.
// ---------------------------------------------------------------------------
__global__ void build_feats_kernel(const float* __restrict__ x) {
    __shared__ float xs[NB][IN_DIM];
    int tid = threadIdx.x;                       // 256 threads
    for (int t = tid; t < NB * IN_DIM; t += 256)
        xs[t >> 8][t & 255] = x[t];
    __syncthreads();

    int i = blockIdx.x;
    if (i < IN_DIM) {
        int j = tid;
        if (j >= i) {
            int off = IN_DIM + i * IN_DIM - (i * (i - 1)) / 2 + (j - i);
            #pragma unroll
            for (int b = 0; b < NB; b++)
                g_feats[b * FEAT + off] = xs[b][i] * xs[b][j];
        }
    } else {
        int j = tid;
        #pragma unroll
        for (int b = 0; b < NB; b++)
            g_feats[b * FEAT + j] = xs[b][j];
    }
}

// ---------------------------------------------------------------------------
// Kernel B: partial[kh][b][r] = dot(feats[b][k in half kh], W[r][same k])
//   grid 2048 = 1024 row-groups x 2 k-halves. Block 64 thr = 2 warps; warp w
//   of k-half kh takes chunk residue (2*kh + w) mod 4 (stride-4 interleave) ->
//   W read exactly once chip-wide. Warp = 8 rows x 8 batches: local traffic
//   2 B per FFMA2 (0.67x of R4). Cross-warp reduce via smem; no atomics.
// ---------------------------------------------------------------------------
__global__ void __launch_bounds__(64, 5)
head_gemm_kernel(const float* __restrict__ W) {
    __shared__ float red[64];        // warp1 partials for cross-warp add

    int warp = threadIdx.x >> 5;     // 0..1
    int lane = threadIdx.x & 31;
    int grp  = blockIdx.x >> 1;      // row group 0..1023
    int kh   = blockIdx.x & 1;       // k half 0..1
    int row0 = grp * 8;
    int res  = 2 * kh + warp;        // chunk residue 0..3
    int nch  = (res <= 2) ? 65 : 64; // chunks 0..258: residue counts

    const float* wp = W + (size_t)row0 * FEAT + res * 128 + lane * 4;
    const float* fp = g_feats + res * 128 + lane * 4;
    const size_t step = 4 * 128;     // 4 chunks of 128 floats

    u64 acc[8][8];
    #pragma unroll
    for (int r = 0; r < 8; r++)
        #pragma unroll
        for (int b = 0; b < 8; b++) acc[r][b] = 0ull;

    #pragma unroll 1
    for (int i = 0; i < nch; i++) {
        ulonglong2 a0 = ldcs128(wp + 0 * FEAT);
        ulonglong2 a1 = ldcs128(wp + 1 * FEAT);
        ulonglong2 a2 = ldcs128(wp + 2 * FEAT);
        ulonglong2 a3 = ldcs128(wp + 3 * FEAT);
        ulonglong2 a4 = ldcs128(wp + 4 * FEAT);
        ulonglong2 a5 = ldcs128(wp + 5 * FEAT);
        ulonglong2 a6 = ldcs128(wp + 6 * FEAT);
        ulonglong2 a7 = ldcs128(wp + 7 * FEAT);
        #pragma unroll
        for (int b = 0; b < 8; b++) {
            ulonglong2 f = ldca128(fp + b * FEAT);
            acc[0][b] = ffma2(a0.x, f.x, acc[0][b]);
            acc[0][b] = ffma2(a0.y, f.y, acc[0][b]);
            acc[1][b] = ffma2(a1.x, f.x, acc[1][b]);
            acc[1][b] = ffma2(a1.y, f.y, acc[1][b]);
            acc[2][b] = ffma2(a2.x, f.x, acc[2][b]);
            acc[2][b] = ffma2(a2.y, f.y, acc[2][b]);
            acc[3][b] = ffma2(a3.x, f.x, acc[3][b]);
            acc[3][b] = ffma2(a3.y, f.y, acc[3][b]);
            acc[4][b] = ffma2(a4.x, f.x, acc[4][b]);
            acc[4][b] = ffma2(a4.y, f.y, acc[4][b]);
            acc[5][b] = ffma2(a5.x, f.x, acc[5][b]);
            acc[5][b] = ffma2(a5.y, f.y, acc[5][b]);
            acc[6][b] = ffma2(a6.x, f.x, acc[6][b]);
            acc[6][b] = ffma2(a6.y, f.y, acc[6][b]);
            acc[7][b] = ffma2(a7.x, f.x, acc[7][b]);
            acc[7][b] = ffma2(a7.y, f.y, acc[7][b]);
        }
        wp += step;
        fp += step;
    }

    // intra-warp reduce: lane0 gets sum for each (r,b)
    float mine[8][8];   // only lane0's values matter after shuffle
    #pragma unroll
    for (int r = 0; r < 8; r++)
        #pragma unroll
        for (int b = 0; b < 8; b++) {
            float v = sum2(acc[r][b]);
            #pragma unroll
            for (int o = 16; o > 0; o >>= 1)
                v += __shfl_xor_sync(0xffffffffu, v, o);
            mine[r][b] = v;
        }

    // cross-warp: warp1 deposits, warp0 adds and writes partial
    if (warp == 1 && lane == 0) {
        #pragma unroll
        for (int r = 0; r < 8; r++)
            #pragma unroll
            for (int b = 0; b < 8; b++)
                red[r * 8 + b] = mine[r][b];
    }
    __syncthreads();
    if (warp == 0 && lane == 0) {
        #pragma unroll
        for (int r = 0; r < 8; r++)
            #pragma unroll
            for (int b = 0; b < 8; b++)
                g_part[kh][b * NROWS + row0 + r] = mine[r][b] + red[r * 8 + b];
    }
}

// ---------------------------------------------------------------------------
// Kernel C: out[b][s][o] = dot(concat[b][s], W_out[o]) + b_out[o]
//   concat[b][s][j] = part0 + part1 + bh at row (j>>6)*2048 + s*64 + (j&63)
// ---------------------------------------------------------------------------
__global__ void out_gemm_kernel(const float* __restrict__ Wout,
                                const float* __restrict__ bout,
                                const float* __restrict__ bh,
                                float* __restrict__ out) {
    __shared__ float cs[256];
    int bs = blockIdx.x;
    int b  = bs >> 5;
    int s  = bs & 31;
    int t  = threadIdx.x;    // 64 threads

    #pragma unroll
    for (int q = 0; q < 4; q++) {
        int j   = t + q * 64;
        int row = (j >> 6) * 2048 + s * 64 + (j & 63);
        int idx = b * NROWS + row;
        cs[j] = g_part[0][idx] + g_part[1][idx] + bh[row];
    }
    __syncthreads();

    const float* wr = Wout + t * 256;
    float sum = bout[t];
    #pragma unroll
    for (int j = 0; j < 256; j += 4) {
        float4 w = *(const float4*)(wr + j);
        sum = fmaf(w.x, cs[j],
              fmaf(w.y, cs[j + 1],
              fmaf(w.z, cs[j + 2],
              fmaf(w.w, cs[j + 3], sum))));
    }
    out[bs * 64 + t] = sum;
}

// ---------------------------------------------------------------------------
extern "C" void kernel_launch(void* const* d_in, const int* in_sizes, int n_in,
                              void* d_out, int out_size) {
    const float* x   = (const float*)d_in[0];   // (8,32,8)
    const float* W   = (const float*)d_in[1];   // (4,2048,33152)
    const float* bh  = (const float*)d_in[2];   // (4,2048)
    const float* Wo  = (const float*)d_in[3];   // (64,256)
    const float* bo  = (const float*)d_in[4];   // (64,)
    float* out = (float*)d_out;                 // (8,32,64)

    build_feats_kernel<<<IN_DIM + 1, 256>>>(x);
    head_gemm_kernel<<<2048, 64>>>(W);
    out_gemm_kernel<<<256, 64>>>(Wo, bo, bh, out);
}

// round 12
// speedup vs baseline: 1.1517x; 1.1517x over previous
#include <cuda_runtime.h>

#define IN_DIM 256
#define FEAT   33152      // 256 + (256 + 256*256)/2 = 259 * 128
#define NB     8          // batch
#define NROWS  8192       // NHEAD * S * D_MODEL
#define KITERS (FEAT / 128)   // 259, exact
#define OUTF   64

typedef unsigned long long u64;

// scratch (allocation-free rule: __device__ globals)
__device__ __align__(16) float g_feats[NB * FEAT];
__device__ __align__(16) float g_head[NB * NROWS];

// packed dual-FMA: d.lo = a.lo*b.lo + c.lo ; d.hi = a.hi*b.hi + c.hi
__device__ __forceinline__ u64 ffma2(u64 a, u64 b, u64 c) {
    u64 d;
    asm("fma.rn.f32x2 %0, %1, %2, %3;" : "=l"(d) : "l"(a), "l"(b), "l"(c));
    return d;
}

__device__ __forceinline__ float sum2(u64 v) {
    union { u64 u; float f[2]; } cvt;
    cvt.u = v;
    return cvt.f[0] + cvt.f[1];
}

// L2-only 16B load for the 1-GB W stream: NO L1 allocation -> L1 stays
// reserved for the feats working set.
__device__ __forceinline__ ulonglong2 ldcg128(const void* p) {
    ulonglong2 v;
    asm volatile("ld.global.cg.v2.u64 {%0, %1}, [%2];"
                 : "=l"(v.x), "=l"(v.y) : "l"(p));
    return v;
}

// default-cached (L1-resident) 16B load for feats
__device__ __forceinline__ ulonglong2 ldca128(const void* p) {
    ulonglong2 v;
    asm("ld.global.ca.v2.u64 {%0, %1}, [%2];"
        : "=l"(v.x), "=l"(v.y) : "l"(p));
    return v;
}

// ---------------------------------------------------------------------------
// Kernel A: build feats = [x_flat | triu(x x^T)] for all 8 batches.
//   grid 129: block p < 128 handles triangle rows p and 255-p (balanced);
//   block 128 does the linear x_flat copy.
// ---------------------------------------------------------------------------
__global__ void build_feats_kernel(const float* __restrict__ x) {
    __shared__ float xs[NB][IN_DIM];
    int tid = threadIdx.x;                       // 256 threads
    for (int t = tid; t < NB * IN_DIM; t += 256)
        xs[t >> 8][t & 255] = x[t];
    __syncthreads();

    int p = blockIdx.x;
    if (p < 128) {
        int j = tid;
        // row i1 = p (long row), row i2 = 255-p (short row)
        #pragma unroll
        for (int h = 0; h < 2; h++) {
            int i = h ? (255 - p) : p;
            if (j >= i) {
                int off = IN_DIM + i * IN_DIM - (i * (i - 1)) / 2 + (j - i);
                #pragma unroll
                for (int b = 0; b < NB; b++)
                    g_feats[b * FEAT + off] = xs[b][i] * xs[b][j];
            }
        }
    } else {
        int j = tid;
        #pragma unroll
        for (int b = 0; b < NB; b++)
            g_feats[b * FEAT + j] = xs[b][j];
    }
}

// ---------------------------------------------------------------------------
// Kernel B: head_out[b][r] = dot(feats[b], W[r]) + bh[r]
//   R4 structure (sync-free, smem-free, 1024 blocks x 64 thr, 4 rows/warp,
//   FFMA2 accumulators), single change: W via ld.global.cg (L2-only) so the
//   1-GB stream never evicts feats from L1.
// ---------------------------------------------------------------------------
__global__ void __launch_bounds__(64, 7)
head_gemm_kernel(const float* __restrict__ W, const float* __restrict__ bh) {
    int warp = threadIdx.x >> 5;                 // 0..1
    int lane = threadIdx.x & 31;
    int row0 = blockIdx.x * 8 + warp * 4;

    const float* w0 = W + (size_t)row0 * FEAT + lane * 4;
    const float* w1 = w0 + FEAT;
    const float* w2 = w1 + FEAT;
    const float* w3 = w2 + FEAT;
    const float* fb = g_feats + lane * 4;

    u64 acc[4][8];
    #pragma unroll
    for (int r = 0; r < 4; r++)
        #pragma unroll
        for (int b = 0; b < 8; b++) acc[r][b] = 0ull;

    #pragma unroll 2
    for (int it = 0; it < KITERS; it++) {
        int k = it * 128;
        ulonglong2 a0 = ldcg128(w0 + k);
        ulonglong2 a1 = ldcg128(w1 + k);
        ulonglong2 a2 = ldcg128(w2 + k);
        ulonglong2 a3 = ldcg128(w3 + k);
        #pragma unroll
        for (int b = 0; b < 8; b++) {
            ulonglong2 f = ldca128(fb + b * FEAT + k);
            acc[0][b] = ffma2(a0.x, f.x, acc[0][b]);
            acc[0][b] = ffma2(a0.y, f.y, acc[0][b]);
            acc[1][b] = ffma2(a1.x, f.x, acc[1][b]);
            acc[1][b] = ffma2(a1.y, f.y, acc[1][b]);
            acc[2][b] = ffma2(a2.x, f.x, acc[2][b]);
            acc[2][b] = ffma2(a2.y, f.y, acc[2][b]);
            acc[3][b] = ffma2(a3.x, f.x, acc[3][b]);
            acc[3][b] = ffma2(a3.y, f.y, acc[3][b]);
        }
    }

    // per-(row,batch): fold k-parity halves, warp-reduce, write
    #pragma unroll
    for (int r = 0; r < 4; r++) {
        #pragma unroll
        for (int b = 0; b < 8; b++) {
            float v = sum2(acc[r][b]);
            #pragma unroll
            for (int o = 16; o > 0; o >>= 1)
                v += __shfl_xor_sync(0xffffffffu, v, o);
            if (lane == 0)
                g_head[b * NROWS + row0 + r] = v + bh[row0 + r];
        }
    }
}

// ---------------------------------------------------------------------------
// Kernel C: out[b][s][o] = dot(concat[b][s], W_out[o]) + b_out[o]
// ---------------------------------------------------------------------------
__global__ void out_gemm_kernel(const float* __restrict__ Wout,
                                const float* __restrict__ bout,
                                float* __restrict__ out) {
    __shared__ float cs[256];
    int bs = blockIdx.x;
    int b  = bs >> 5;
    int s  = bs & 31;
    int t  = threadIdx.x;    // 64 threads

    #pragma unroll
    for (int q = 0; q < 4; q++) {
        int j = t + q * 64;
        cs[j] = g_head[b * NROWS + (j >> 6) * 2048 + s * 64 + (j & 63)];
    }
    __syncthreads();

    const float* wr = Wout + t * 256;
    float sum = bout[t];
    #pragma unroll
    for (int j = 0; j < 256; j += 4) {
        float4 w = *(const float4*)(wr + j);
        sum = fmaf(w.x, cs[j],
              fmaf(w.y, cs[j + 1],
              fmaf(w.z, cs[j + 2],
              fmaf(w.w, cs[j + 3], sum))));
    }
    out[bs * 64 + t] = sum;
}

// ---------------------------------------------------------------------------
extern "C" void kernel_launch(void* const* d_in, const int* in_sizes, int n_in,
                              void* d_out, int out_size) {
    const float* x   = (const float*)d_in[0];   // (8,32,8)
    const float* W   = (const float*)d_in[1];   // (4,2048,33152)
    const float* bh  = (const float*)d_in[2];   // (4,2048)
    const float* Wo  = (const float*)d_in[3];   // (64,256)
    const float* bo  = (const float*)d_in[4];   // (64,)
    float* out = (float*)d_out;                 // (8,32,64)

    build_feats_kernel<<<129, 256>>>(x);
    head_gemm_kernel<<<NROWS / 8, 64>>>(W, bh);
    out_gemm_kernel<<<256, 64>>>(Wo, bo, out);
}